// round 1
// baseline (speedup 1.0000x reference)
#include <cuda_runtime.h>

// Problem shape (fixed by setup_inputs): N=100000, D=128, E=500000, R=500
#define D 128
#define MAX_N 100000

// Scratch: per-node inverse L1 norm (allocation-free per harness rules)
__device__ float g_inv_norm[MAX_N];

// Pass 1: one warp per node row. inv_norm[n] = 1 / max(sum|z[n,:]|, 1e-12)
__global__ void __launch_bounds__(256) norm_kernel(const float* __restrict__ z, int N) {
    int row  = (blockIdx.x * blockDim.x + threadIdx.x) >> 5;
    int lane = threadIdx.x & 31;
    if (row >= N) return;
    float4 v = reinterpret_cast<const float4*>(z + (size_t)row * D)[lane];
    float s = fabsf(v.x) + fabsf(v.y) + fabsf(v.z) + fabsf(v.w);
    #pragma unroll
    for (int o = 16; o; o >>= 1) s += __shfl_xor_sync(0xffffffffu, s, o);
    if (lane == 0) g_inv_norm[row] = 1.0f / fmaxf(s, 1e-12f);
}

// Pass 2: one warp per edge. Lane i holds 4 consecutive dims (float4),
// so each row read is one coalesced 512B transaction per warp.
// score = -sum_d | h_d*inv_h + r_d - t_d*inv_t |
__global__ void __launch_bounds__(256) edge_kernel(const float* __restrict__ z,
                                                   const int*   __restrict__ edge_index, // [2,E]
                                                   const int*   __restrict__ edge_type,  // [E]
                                                   const float* __restrict__ rel_emb,    // [R,D]
                                                   float*       __restrict__ out,        // [E]
                                                   int E) {
    int e    = (blockIdx.x * blockDim.x + threadIdx.x) >> 5;
    int lane = threadIdx.x & 31;
    if (e >= E) return;

    int h = edge_index[e];
    int t = edge_index[E + e];
    int r = edge_type[e];

    float inv_h = g_inv_norm[h];
    float inv_t = g_inv_norm[t];

    float4 hv = reinterpret_cast<const float4*>(z       + (size_t)h * D)[lane];
    float4 tv = reinterpret_cast<const float4*>(z       + (size_t)t * D)[lane];
    float4 rv = reinterpret_cast<const float4*>(rel_emb + (size_t)r * D)[lane];

    float s = fabsf(fmaf(hv.x, inv_h, rv.x) - tv.x * inv_t)
            + fabsf(fmaf(hv.y, inv_h, rv.y) - tv.y * inv_t)
            + fabsf(fmaf(hv.z, inv_h, rv.z) - tv.z * inv_t)
            + fabsf(fmaf(hv.w, inv_h, rv.w) - tv.w * inv_t);

    #pragma unroll
    for (int o = 16; o; o >>= 1) s += __shfl_xor_sync(0xffffffffu, s, o);
    if (lane == 0) out[e] = -s;
}

extern "C" void kernel_launch(void* const* d_in, const int* in_sizes, int n_in,
                              void* d_out, int out_size) {
    const float* z          = (const float*)d_in[0];   // [N, 128]
    const int*   edge_index = (const int*)  d_in[1];   // [2, E] (int32; jax x64 disabled)
    const int*   edge_type  = (const int*)  d_in[2];   // [E]
    const float* rel_emb    = (const float*)d_in[3];   // [R, 128]
    float*       out        = (float*)d_out;

    int N = in_sizes[0] / D;     // 100000
    int E = in_sizes[2];         // 500000

    // Pass 1: per-node inverse L1 norms. 8 warps/block -> N/8 blocks.
    {
        int warps_per_block = 8;
        int blocks = (N + warps_per_block - 1) / warps_per_block;
        norm_kernel<<<blocks, warps_per_block * 32>>>(z, N);
    }

    // Pass 2: per-edge score. 8 warps/block -> E/8 blocks.
    {
        int warps_per_block = 8;
        int blocks = (E + warps_per_block - 1) / warps_per_block;
        edge_kernel<<<blocks, warps_per_block * 32>>>(z, edge_index, edge_type,
                                                      rel_emb, out, E);
    }
}

// round 2
// speedup vs baseline: 1.3351x; 1.3351x over previous
#include <cuda_runtime.h>
#include <cuda_fp16.h>

// Problem shape (fixed by setup_inputs): N=100000, D=128, E=500000, R=500
#define D 128
#define MAX_N 100000
#define MAX_R 500

// Scratch (allocation-free): L1-normalized z in fp16, rel_emb in fp16.
__device__ __half g_zn[(size_t)MAX_N * D];    // 25.6 MB
__device__ __half g_rel[(size_t)MAX_R * D];   // 128 KB

// Pass 1a: one warp per node row. zn[n,:] = z[n,:] / max(sum|z[n,:]|, 1e-12), fp16.
__global__ void __launch_bounds__(256) norm_kernel(const float* __restrict__ z, int N) {
    int row  = (blockIdx.x * blockDim.x + threadIdx.x) >> 5;
    int lane = threadIdx.x & 31;
    if (row >= N) return;
    float4 v = reinterpret_cast<const float4*>(z + (size_t)row * D)[lane];
    float s = fabsf(v.x) + fabsf(v.y) + fabsf(v.z) + fabsf(v.w);
    #pragma unroll
    for (int o = 16; o; o >>= 1) s += __shfl_xor_sync(0xffffffffu, s, o);
    float inv = 1.0f / fmaxf(s, 1e-12f);
    __half2 h0 = __floats2half2_rn(v.x * inv, v.y * inv);
    __half2 h1 = __floats2half2_rn(v.z * inv, v.w * inv);
    uint2 packed;
    packed.x = *reinterpret_cast<unsigned*>(&h0);
    packed.y = *reinterpret_cast<unsigned*>(&h1);
    reinterpret_cast<uint2*>(g_zn + (size_t)row * D)[lane] = packed;
}

// Pass 1b: convert rel_emb [R,128] fp32 -> fp16 (64K elements).
__global__ void rel_convert_kernel(const float* __restrict__ rel, int n_half2) {
    int i = blockIdx.x * blockDim.x + threadIdx.x;
    if (i >= n_half2) return;
    float2 v = reinterpret_cast<const float2*>(rel)[i];
    reinterpret_cast<__half2*>(g_rel)[i] = __floats2half2_rn(v.x, v.y);
}

// Pass 2: 2 edges per warp, 16 lanes per edge. Each lane loads one uint4
// (8 halfs = 16B) from each of the 3 rows -> 256B coalesced per row group.
// All arithmetic in fp32 after half2->float2 conversion; only storage is fp16.
__global__ void __launch_bounds__(256) edge_kernel(const int*  __restrict__ edge_index, // [2,E]
                                                   const int*  __restrict__ edge_type,  // [E]
                                                   float*      __restrict__ out,        // [E]
                                                   int E) {
    int warp_g  = (blockIdx.x * blockDim.x + threadIdx.x) >> 5;
    int lane    = threadIdx.x & 31;
    int half_id = lane >> 4;       // which edge within the warp
    int sub     = lane & 15;       // lane within 16-lane group

    int e = warp_g * 2 + half_id;
    if (e >= E) return;

    int h = edge_index[e];
    int t = edge_index[E + e];
    int r = edge_type[e];

    // 16 lanes x 16B = 256B per row, fully coalesced per group.
    uint4 hv = reinterpret_cast<const uint4*>(g_zn  + (size_t)h * D)[sub];
    uint4 tv = reinterpret_cast<const uint4*>(g_zn  + (size_t)t * D)[sub];
    uint4 rv = reinterpret_cast<const uint4*>(g_rel + (size_t)r * D)[sub];

    const __half2* h2 = reinterpret_cast<const __half2*>(&hv);
    const __half2* t2 = reinterpret_cast<const __half2*>(&tv);
    const __half2* r2 = reinterpret_cast<const __half2*>(&rv);

    float s = 0.0f;
    #pragma unroll
    for (int j = 0; j < 4; j++) {
        float2 hf = __half22float2(h2[j]);
        float2 tf = __half22float2(t2[j]);
        float2 rf = __half22float2(r2[j]);
        s += fabsf(hf.x + rf.x - tf.x) + fabsf(hf.y + rf.y - tf.y);
    }

    // Reduce across the 16-lane group (xor 8,4,2,1 stays inside each half-warp).
    #pragma unroll
    for (int o = 8; o; o >>= 1) s += __shfl_xor_sync(0xffffffffu, s, o);
    if (sub == 0) out[e] = -s;
}

extern "C" void kernel_launch(void* const* d_in, const int* in_sizes, int n_in,
                              void* d_out, int out_size) {
    const float* z          = (const float*)d_in[0];   // [N, 128]
    const int*   edge_index = (const int*)  d_in[1];   // [2, E] int32
    const int*   edge_type  = (const int*)  d_in[2];   // [E]
    const float* rel_emb    = (const float*)d_in[3];   // [R, 128]
    float*       out        = (float*)d_out;

    int N = in_sizes[0] / D;      // 100000
    int E = in_sizes[2];          // 500000
    int R = in_sizes[3] / D;      // 500

    // Pass 1a: per-node L1 normalize -> fp16 table. 8 warps/block.
    {
        int blocks = (N + 7) / 8;
        norm_kernel<<<blocks, 256>>>(z, N);
    }
    // Pass 1b: rel_emb fp32 -> fp16.
    {
        int n_half2 = R * D / 2;
        int blocks = (n_half2 + 255) / 256;
        rel_convert_kernel<<<blocks, 256>>>(rel_emb, n_half2);
    }
    // Pass 2: per-edge score, 2 edges per warp.
    {
        int n_warps = (E + 1) / 2;
        int blocks = (n_warps + 7) / 8;   // 8 warps = 256 threads per block
        edge_kernel<<<blocks, 256>>>(edge_index, edge_type, out, E);
    }
}